// round 11
// baseline (speedup 1.0000x reference)
#include <cuda_runtime.h>

#define TT 336

// ---------------- device scratch ----------------
__device__ float dW1g[2 * 80 * 280];        // [dir][k][up(35)][gate(4)][2], i/f/o prescaled 0.5
__device__ float dB1g[2 * 280];             // [dir][up][gate][2]
__device__ float dW2g[2 * 161 * 88];        // [dir][k][up(11)][gate(4)][2]
__device__ float dB2g[2 * 88];
__device__ float dH1T[64 * 336 * 140 * 32]; // [bblk][t][k(140)][r(32)]
__device__ float dH2[64 * 336 * 42 * 32];   // [bblk][t][u(42)][r(32)]

typedef unsigned long long ull;

// ---------------- f32x2 helpers ----------------
__device__ __forceinline__ ull pk2(float v) {
    ull r;
    asm("mov.b64 %0, {%1, %1};" : "=l"(r) : "f"(v));
    return r;
}
__device__ __forceinline__ float2 up2(ull v) {
    float2 r;
    asm("mov.b64 {%0, %1}, %2;" : "=f"(r.x), "=f"(r.y) : "l"(v));
    return r;
}
__device__ __forceinline__ void fma2(ull& d, ull a, ull b) {
    asm("fma.rn.f32x2 %0, %1, %2, %3;" : "=l"(d) : "l"(a), "l"(b), "l"(d));
}
__device__ __forceinline__ float tanha(float x) {
    float y;
    asm("tanh.approx.f32 %0, %1;" : "=f"(y) : "f"(x));
    return y;
}
// i/f/o pre-acts prescaled by 0.5 -> sigmoid(z) = 0.5 + 0.5*tanh(z/2)
__device__ __forceinline__ void lstm_act(float2 yi, float2 yf, float2 yg, float2 yo,
                                         float2& c, float2& h) {
    float six = 0.5f + 0.5f * tanha(yi.x), siy = 0.5f + 0.5f * tanha(yi.y);
    float sfx = 0.5f + 0.5f * tanha(yf.x), sfy = 0.5f + 0.5f * tanha(yf.y);
    float tgx = tanha(yg.x), tgy = tanha(yg.y);
    float sox = 0.5f + 0.5f * tanha(yo.x), soy = 0.5f + 0.5f * tanha(yo.y);
    c.x = sfx * c.x + six * tgx;
    c.y = sfy * c.y + siy * tgy;
    h.x = sox * tanha(c.x);
    h.y = soy * tanha(c.y);
}

// ---------------- weight prep (interleaved [k][up][gate][2], 0.5 prescale on i/f/o) ----------------
__global__ void prep1(const float* wfih, const float* wfhh, const float* bfih, const float* bfhh,
                      const float* wbih, const float* wbhh, const float* bbih, const float* bbhh) {
    int idx = blockIdx.x * blockDim.x + threadIdx.x;
    if (idx < 2 * 80 * 280) {
        int d = idx / 22400, rem = idx % 22400;
        int k = rem / 280, j = rem % 280;
        int up = j / 8, g = (j / 2) % 4, e = j & 1;
        int u = up * 2 + e, row = g * 70 + u;
        const float* wih = d ? wbih : wfih;
        const float* whh = d ? wbhh : wfhh;
        float v = (k < 10) ? wih[row * 10 + k] : whh[row * 70 + (k - 10)];
        if (g != 2) v *= 0.5f;
        dW1g[idx] = v;
    }
    if (idx < 2 * 280) {
        int d = idx / 280, j = idx % 280;
        int up = j / 8, g = (j / 2) % 4, e = j & 1;
        int u = up * 2 + e, row = g * 70 + u;
        const float* bih = d ? bbih : bfih;
        const float* bhh = d ? bbhh : bfhh;
        float v = bih[row] + bhh[row];
        if (g != 2) v *= 0.5f;
        dB1g[idx] = v;
    }
}

__global__ void prep2(const float* wfih, const float* wfhh, const float* bfih, const float* bfhh,
                      const float* wbih, const float* wbhh, const float* bbih, const float* bbhh) {
    int idx = blockIdx.x * blockDim.x + threadIdx.x;
    if (idx < 2 * 161 * 88) {
        int d = idx / (161 * 88), rem = idx % (161 * 88);
        int k = rem / 88, j = rem % 88;
        int up = j / 8, g = (j / 2) % 4, e = j & 1;
        int u = up * 2 + e;
        float v = 0.f;
        if (u < 21) {
            int row = g * 21 + u;
            const float* wih = d ? wbih : wfih;
            const float* whh = d ? wbhh : wfhh;
            v = (k < 140) ? wih[row * 140 + k] : whh[row * 21 + (k - 140)];
            if (g != 2) v *= 0.5f;
        }
        dW2g[idx] = v;
    }
    if (idx < 2 * 88) {
        int d = idx / 88, j = idx % 88;
        int up = j / 8, g = (j / 2) % 4, e = j & 1;
        int u = up * 2 + e;
        float v = 0.f;
        if (u < 21) {
            int row = g * 21 + u;
            const float* bih = d ? bbih : bfih;
            const float* bhh = d ? bbhh : bfhh;
            v = bih[row] + bhh[row];
            if (g != 2) v *= 0.5f;
        }
        dB2g[idx] = v;
    }
}

// ---------------- layer 1: F=10 -> H=70, bidirectional ----------------
// grid (64, 2), 560 threads = 2 k-groups x 280 (rg 0..7 [4 rows] x up 0..34).
// Acts stored DUPLICATED [k80][r64] ({v,v} pairs): the two act LDS.128 yield
// f32x2 operands directly (no pk2 MOVs). Crossbar: 6 wf per 32 fma-cyc - safe.
__global__ __launch_bounds__(560, 1) void lstm1(const float* __restrict__ x) {
    extern __shared__ float sm[];
    float* sW = sm;                  // 22400
    float* sB = sW + 22400;          // 280
    float* sA = sB + 280;            // 2 * 5120  (dup [k80][r64] per buffer)
    float* sRed = sA + 10240;        // 2 grp * 8 j * 280 q * 2 = 8960
    const int dir = blockIdx.y, bblk = blockIdx.x;
    const int b0 = bblk * 32;
    const int tid = threadIdx.x;

    const float* gW = dW1g + dir * 22400;
    for (int i = tid; i < 22400; i += 560) sW[i] = gW[i];
    if (tid < 280) sB[tid] = dB1g[dir * 280 + tid];
    for (int i = tid; i < 70 * 64; i += 560) sA[10 * 64 + i] = 0.f;   // h-region buf0

    const int grp = (tid >= 280) ? 1 : 0;
    const int q = tid - 280 * grp;
    const int rg = q & 7, up = q >> 3;
    const int r0 = rg * 4, u0 = up * 2;
    const int rown = r0 + 2 * grp;   // owned rows: rown, rown+1
    const int jo = 2 * grp;          // owned acc idx
    const int jn = 2 - 2 * grp;      // non-owned acc idx

    // stage x(t0) dup into buffer 0 (1 value per thread, tid<320)
    const int xrow = tid / 10, xf = tid % 10;
    const bool hasx = tid < 320;
    if (hasx) {
        float v = x[((b0 + xrow) * TT + (dir ? TT - 1 : 0)) * 10 + xf];
        *(float2*)&sA[xf * 64 + 2 * xrow] = make_float2(v, v);
    }
    float xr = 0.f;
    if (hasx) xr = x[((b0 + xrow) * TT + (dir ? TT - 2 : 1)) * 10 + xf];

    float2 c[2];
    c[0] = make_float2(0.f, 0.f);
    c[1] = make_float2(0.f, 0.f);
    const float* pw = sW + grp * 40 * 280 + up * 8;
    float* sRW = sRed + grp * 8 * 560;            // write: [j][q][2]
    const float* sRR = sRed + (1 - grp) * 8 * 560;
    __syncthreads();

    float2 bf[4];
#pragma unroll
    for (int g = 0; g < 4; g++) bf[g] = *(const float2*)&sB[up * 8 + g * 2];

    int p = 0;
    for (int s = 0; s < TT; s++) {
        const int t = dir ? TT - 1 - s : s;
        const float* pa = sA + p * 5120 + grp * 2560 + 2 * r0;   // dup offset

        ull acc[4][4];
#pragma unroll
        for (int r = 0; r < 4; r++)
#pragma unroll
            for (int g = 0; g < 4; g++) acc[r][g] = 0ull;

#pragma unroll 8
        for (int k = 0; k < 40; k++) {
            ulonglong2 a01 = *(const ulonglong2*)(pa + k * 64);       // {v0,v0},{v1,v1}
            ulonglong2 a23 = *(const ulonglong2*)(pa + k * 64 + 4);   // {v2,v2},{v3,v3}
            ulonglong2 w01 = *(const ulonglong2*)(pw + k * 280);      // gate pairs 0,1 (bcast)
            ulonglong2 w23 = *(const ulonglong2*)(pw + k * 280 + 4);  // gate pairs 2,3 (bcast)
            fma2(acc[0][0], a01.x, w01.x); fma2(acc[0][1], a01.x, w01.y);
            fma2(acc[0][2], a01.x, w23.x); fma2(acc[0][3], a01.x, w23.y);
            fma2(acc[1][0], a01.y, w01.x); fma2(acc[1][1], a01.y, w01.y);
            fma2(acc[1][2], a01.y, w23.x); fma2(acc[1][3], a01.y, w23.y);
            fma2(acc[2][0], a23.x, w01.x); fma2(acc[2][1], a23.x, w01.y);
            fma2(acc[2][2], a23.x, w23.x); fma2(acc[2][3], a23.x, w23.y);
            fma2(acc[3][0], a23.y, w01.x); fma2(acc[3][1], a23.y, w01.y);
            fma2(acc[3][2], a23.y, w23.x); fma2(acc[3][3], a23.y, w23.y);
        }

        // write non-owned 2-row partials (coalesced [j][q] layout)
#pragma unroll
        for (int j = 0; j < 8; j++)
            *(ull*)&sRW[j * 560 + q * 2] = acc[jn + (j >> 2)][j & 3];
        __syncthreads();

        float2 hv[2];
#pragma unroll
        for (int jj = 0; jj < 2; jj++) {
            float2 y[4];
#pragma unroll
            for (int g = 0; g < 4; g++) {
                float2 own = up2(acc[jo + jj][g]);
                float2 pe = up2(*(const ull*)&sRR[(jj * 4 + g) * 560 + q * 2]);
                y[g] = make_float2(own.x + pe.x + bf[g].x, own.y + pe.y + bf[g].y);
            }
            lstm_act(y[0], y[1], y[2], y[3], c[jj], hv[jj]);
        }

        // h(t) -> other buffer (DUP) + global blocked-transposed (non-dup)
        float* nb = sA + (p ^ 1) * 5120;
#pragma unroll
        for (int jj = 0; jj < 2; jj++) {
            int rr = rown + jj;
            *(float2*)&nb[(10 + u0) * 64 + 2 * rr] = make_float2(hv[jj].x, hv[jj].x);
            *(float2*)&nb[(11 + u0) * 64 + 2 * rr] = make_float2(hv[jj].y, hv[jj].y);
        }
        {
            size_t gb = ((size_t)(bblk * TT + t) * 140 + dir * 70 + u0) * 32 + rown;
            *(float2*)&dH1T[gb]      = make_float2(hv[0].x, hv[1].x);
            *(float2*)&dH1T[gb + 32] = make_float2(hv[0].y, hv[1].y);
        }
        // stage x(t+1) dup + prefetch x(t+2)
        if (hasx) {
            *(float2*)&nb[xf * 64 + 2 * xrow] = make_float2(xr, xr);
            if (s + 2 < TT) {
                int tn = dir ? TT - 3 - s : s + 2;
                xr = x[((b0 + xrow) * TT + tn) * 10 + xf];
            }
        }
        __syncthreads();
        p ^= 1;
    }
}

// ---------------- layer 2: 140 -> H=21 (pad 22), bidirectional ----------------
// grid (64, 2), 704 threads = 4 k-groups x 176 (rg 0..15 [2 rows] x up 0..10).
// 22 warps/SM (5.5/SMSP). Non-dup acts [k161][r32]; act LDS.64 + 2 pk2 MOVs;
// weight LDS.128 broadcast. Thread accumulates 2 rows x 2 units x 4 gates over
// its ~40-k quarter; 3-slot single-stage reduction; grp0 finalizes row r0,
// grp1 row r0+1, grp2/grp3 donate only.
#define L2_KLOOP(KN)                                                          \
    _Pragma("unroll 8")                                                       \
    for (int k = 0; k < (KN); k++) {                                          \
        float2 av = *(const float2*)(pa + k * 32);                            \
        ull a0 = pk2(av.x), a1 = pk2(av.y);                                   \
        ulonglong2 w01 = *(const ulonglong2*)(pw + k * 88);                   \
        ulonglong2 w23 = *(const ulonglong2*)(pw + k * 88 + 4);               \
        fma2(acc[0][0], a0, w01.x); fma2(acc[0][1], a0, w01.y);               \
        fma2(acc[0][2], a0, w23.x); fma2(acc[0][3], a0, w23.y);               \
        fma2(acc[1][0], a1, w01.x); fma2(acc[1][1], a1, w01.y);               \
        fma2(acc[1][2], a1, w23.x); fma2(acc[1][3], a1, w23.y);               \
    }

// sRed float index for [slot(3)][j(2)][g(4)][q(176)][2]
#define SRED2(slot, j, g, q) ((((((slot) * 2 + (j)) * 4 + (g)) * 176) + (q)) * 2)

__global__ __launch_bounds__(704, 1) void lstm2() {
    extern __shared__ float sm[];
    float* sW = sm;                  // 14168
    float* sB = sW + 14168;          // 88
    float* sA = sB + 88;             // 2 * 5152  ([k161][r32] per buffer)
    float* sRed = sA + 10304;        // 3*2*4*176*2 = 8448
    const int dir = blockIdx.y, bblk = blockIdx.x;
    const int tid = threadIdx.x;

    const float* gW = dW2g + dir * 14168;
    for (int i = tid; i < 14168; i += 704) sW[i] = gW[i];
    if (tid < 88) sB[tid] = dB2g[dir * 88 + tid];
    for (int i = tid; i < 21 * 32; i += 704) sA[140 * 32 + i] = 0.f;   // h-region buf0

    // stage h1(t0): 1120 float4 contiguous
    {
        int t0 = dir ? TT - 1 : 0;
        const float4* src = (const float4*)&dH1T[(size_t)(bblk * TT + t0) * 4480];
        float4* dst = (float4*)sA;
        dst[tid < 1120 ? tid : 0] = src[tid < 1120 ? tid : 0];
        if (tid < 416) dst[tid + 704] = src[tid + 704];
    }

    const int grp = tid / 176;
    const int q = tid - 176 * grp;
    const int rg = q & 15, up = q >> 4;
    const int r0 = rg * 2, u0 = up * 2;

    float2 c = make_float2(0.f, 0.f);
    const int kbeg = grp * 40;
    const int kcnt = (grp == 3) ? 41 : 40;
    const float* pw = sW + kbeg * 88 + up * 8;

    // prefetch h1(t1)
    float4 pf0, pf1;
    {
        int t1 = dir ? TT - 2 : 1;
        const float4* src = (const float4*)&dH1T[(size_t)(bblk * TT + t1) * 4480];
        pf0 = src[tid < 1120 ? tid : 0];
        if (tid < 416) pf1 = src[tid + 704];
    }
    __syncthreads();

    float2 bf[4];
#pragma unroll
    for (int g = 0; g < 4; g++) bf[g] = *(const float2*)&sB[up * 8 + g * 2];

    int p = 0;
    for (int s = 0; s < TT; s++) {
        const int t = dir ? TT - 1 - s : s;
        const float* pa = sA + p * 5152 + kbeg * 32 + r0;

        ull acc[2][4];
#pragma unroll
        for (int r = 0; r < 2; r++)
#pragma unroll
            for (int g = 0; g < 4; g++) acc[r][g] = 0ull;

        if (kcnt == 40) { L2_KLOOP(40) } else { L2_KLOOP(41) }

        // donations (coalesced along q)
        if (grp == 0) {
#pragma unroll
            for (int g = 0; g < 4; g++) *(ull*)&sRed[SRED2(0, 1, g, q)] = acc[1][g];
        } else if (grp == 1) {
#pragma unroll
            for (int g = 0; g < 4; g++) *(ull*)&sRed[SRED2(0, 0, g, q)] = acc[0][g];
        } else {
            int sl = grp - 1;
#pragma unroll
            for (int g = 0; g < 4; g++) *(ull*)&sRed[SRED2(sl, 0, g, q)] = acc[0][g];
#pragma unroll
            for (int g = 0; g < 4; g++) *(ull*)&sRed[SRED2(sl, 1, g, q)] = acc[1][g];
        }
        __syncthreads();

        float* nb = sA + (p ^ 1) * 5152;
        if (grp <= 1) {
            const int j = grp;               // finalized row index within pair
            float2 y[4];
#pragma unroll
            for (int g = 0; g < 4; g++) {
                float2 own = up2(acc[j][g]);
                float2 p0 = up2(*(const ull*)&sRed[SRED2(0, j, g, q)]);
                float2 p1 = up2(*(const ull*)&sRed[SRED2(1, j, g, q)]);
                float2 p2 = up2(*(const ull*)&sRed[SRED2(2, j, g, q)]);
                y[g] = make_float2(own.x + p0.x + p1.x + p2.x + bf[g].x,
                                   own.y + p0.y + p1.y + p2.y + bf[g].y);
            }
            float2 h;
            lstm_act(y[0], y[1], y[2], y[3], c, h);

            const int rr = r0 + j;
            nb[(140 + u0) * 32 + rr] = h.x;
            if (u0 + 1 < 21) nb[(141 + u0) * 32 + rr] = h.y;
            size_t ob = ((size_t)(bblk * TT + t) * 42 + dir * 21 + u0) * 32 + rr;
            dH2[ob] = h.x;
            if (u0 + 1 < 21) dH2[ob + 32] = h.y;
        }

        // stage h1(t+1) into other buffer (contiguous STS.128)
        if (s + 1 < TT) {
            float4* dst = (float4*)nb;
            if (tid < 1120) dst[tid] = pf0;
            if (tid < 416) dst[tid + 704] = pf1;
        }
        // prefetch h1(t+2)
        if (s + 2 < TT) {
            int tn = dir ? TT - 3 - s : s + 2;
            const float4* src = (const float4*)&dH1T[(size_t)(bblk * TT + tn) * 4480];
            pf0 = src[tid < 1120 ? tid : 0];
            if (tid < 416) pf1 = src[tid + 704];
        }
        __syncthreads();
        p ^= 1;
    }
}

// ---------------- dense head: 42 -> relu 30 -> relu 20 -> 1 ----------------
// grid (64, 84): CTA = (bblk, 4-t tile). Stages the [4t][42u][32r] tile through
// SMEM (coalesced LDG + coalesced LDS), 128 threads = one position each.
__global__ __launch_bounds__(128) void dense_head(const float* __restrict__ wd1, const float* __restrict__ bd1,
                                                  const float* __restrict__ wd2, const float* __restrict__ bd2,
                                                  const float* __restrict__ wo, const float* __restrict__ bo,
                                                  float* __restrict__ out) {
    __shared__ float sT[4 * 42 * 32];
    __shared__ float sW1[30 * 42], sb1[30], sW2[20 * 30], sb2[20], swo[20], sbo[1];
    const int tid = threadIdx.x;
    const int bblk = blockIdx.x, t0 = blockIdx.y * 4;

    {
        const float4* src = (const float4*)&dH2[(size_t)(bblk * TT + t0) * 1344];
        float4* dst = (float4*)sT;
#pragma unroll
        for (int j = 0; j < 11; j++) {
            int i = tid + j * 128;
            if (i < 1344) dst[i] = src[i];
        }
    }
    for (int i = tid; i < 1260; i += 128) sW1[i] = wd1[i];
    for (int i = tid; i < 600; i += 128) sW2[i] = wd2[i];
    if (tid < 30) sb1[tid] = bd1[tid];
    if (tid < 20) { sb2[tid] = bd2[tid]; swo[tid] = wo[tid]; }
    if (tid == 0) sbo[0] = bo[0];
    __syncthreads();

    const int t = tid >> 5, r = tid & 31;
    float in[42];
#pragma unroll
    for (int u = 0; u < 42; u++) in[u] = sT[(t * 42 + u) * 32 + r];

    float a[30];
#pragma unroll
    for (int j = 0; j < 30; j++) {
        float s = sb1[j];
#pragma unroll
        for (int k = 0; k < 42; k++) s += in[k] * sW1[j * 42 + k];
        a[j] = fmaxf(s, 0.f);
    }
    float o = sbo[0];
#pragma unroll
    for (int j = 0; j < 20; j++) {
        float s = sb2[j];
#pragma unroll
        for (int k = 0; k < 30; k++) s += a[k] * sW2[j * 30 + k];
        o += fmaxf(s, 0.f) * swo[j];
    }
    out[(size_t)(bblk * 32 + r) * TT + t0 + t] = o;
}

// ---------------- launch ----------------
extern "C" void kernel_launch(void* const* d_in, const int* in_sizes, int n_in,
                              void* d_out, int out_size) {
    const float* x = (const float*)d_in[0];

    const int smem1 = (22400 + 280 + 2 * 5120 + 8960) * 4;   // 167520 B
    const int smem2 = (14168 + 88 + 2 * 5152 + 8448) * 4;    // 132032 B
    cudaFuncSetAttribute(lstm1, cudaFuncAttributeMaxDynamicSharedMemorySize, smem1);
    cudaFuncSetAttribute(lstm2, cudaFuncAttributeMaxDynamicSharedMemorySize, smem2);

    prep1<<<175, 256>>>((const float*)d_in[1], (const float*)d_in[2], (const float*)d_in[3], (const float*)d_in[4],
                        (const float*)d_in[5], (const float*)d_in[6], (const float*)d_in[7], (const float*)d_in[8]);
    prep2<<<111, 256>>>((const float*)d_in[9], (const float*)d_in[10], (const float*)d_in[11], (const float*)d_in[12],
                        (const float*)d_in[13], (const float*)d_in[14], (const float*)d_in[15], (const float*)d_in[16]);

    lstm1<<<dim3(64, 2), 560, smem1>>>(x);
    lstm2<<<dim3(64, 2), 704, smem2>>>();

    dense_head<<<dim3(64, 84), 128>>>((const float*)d_in[17], (const float*)d_in[18],
                                      (const float*)d_in[19], (const float*)d_in[20],
                                      (const float*)d_in[21], (const float*)d_in[22],
                                      (float*)d_out);
}

// round 12
// speedup vs baseline: 1.4007x; 1.4007x over previous
#include <cuda_runtime.h>

#define TT 336

// ---------------- device scratch ----------------
__device__ float dW1g[2 * 80 * 280];        // [dir][k][up(35)][gate(4)][2], i/f/o prescaled 0.5
__device__ float dB1g[2 * 280];             // [dir][up][gate][2]
__device__ float dW2g[2 * 161 * 88];        // [dir][k][up(11)][gate(4)][2]
__device__ float dB2g[2 * 88];
__device__ float dH1T[64 * 336 * 140 * 32]; // [bblk][t][k(140)][r(32)]
__device__ float dH2[64 * 336 * 42 * 32];   // [bblk][t][u(42)][r(32)]

typedef unsigned long long ull;

// ---------------- f32x2 helpers ----------------
__device__ __forceinline__ ull pk2(float v) {
    ull r;
    asm("mov.b64 %0, {%1, %1};" : "=l"(r) : "f"(v));
    return r;
}
__device__ __forceinline__ float2 up2(ull v) {
    float2 r;
    asm("mov.b64 {%0, %1}, %2;" : "=f"(r.x), "=f"(r.y) : "l"(v));
    return r;
}
__device__ __forceinline__ void fma2(ull& d, ull a, ull b) {
    asm("fma.rn.f32x2 %0, %1, %2, %3;" : "=l"(d) : "l"(a), "l"(b), "l"(d));
}
__device__ __forceinline__ float tanha(float x) {
    float y;
    asm("tanh.approx.f32 %0, %1;" : "=f"(y) : "f"(x));
    return y;
}
// i/f/o pre-acts prescaled by 0.5 -> sigmoid(z) = 0.5 + 0.5*tanh(z/2)
__device__ __forceinline__ void lstm_act(float2 yi, float2 yf, float2 yg, float2 yo,
                                         float2& c, float2& h) {
    float six = 0.5f + 0.5f * tanha(yi.x), siy = 0.5f + 0.5f * tanha(yi.y);
    float sfx = 0.5f + 0.5f * tanha(yf.x), sfy = 0.5f + 0.5f * tanha(yf.y);
    float tgx = tanha(yg.x), tgy = tanha(yg.y);
    float sox = 0.5f + 0.5f * tanha(yo.x), soy = 0.5f + 0.5f * tanha(yo.y);
    c.x = sfx * c.x + six * tgx;
    c.y = sfy * c.y + siy * tgy;
    h.x = sox * tanha(c.x);
    h.y = soy * tanha(c.y);
}

// ---------------- weight prep (interleaved [k][up][gate][2], 0.5 prescale on i/f/o) ----------------
__global__ void prep1(const float* wfih, const float* wfhh, const float* bfih, const float* bfhh,
                      const float* wbih, const float* wbhh, const float* bbih, const float* bbhh) {
    int idx = blockIdx.x * blockDim.x + threadIdx.x;
    if (idx < 2 * 80 * 280) {
        int d = idx / 22400, rem = idx % 22400;
        int k = rem / 280, j = rem % 280;
        int up = j / 8, g = (j / 2) % 4, e = j & 1;
        int u = up * 2 + e, row = g * 70 + u;
        const float* wih = d ? wbih : wfih;
        const float* whh = d ? wbhh : wfhh;
        float v = (k < 10) ? wih[row * 10 + k] : whh[row * 70 + (k - 10)];
        if (g != 2) v *= 0.5f;
        dW1g[idx] = v;
    }
    if (idx < 2 * 280) {
        int d = idx / 280, j = idx % 280;
        int up = j / 8, g = (j / 2) % 4, e = j & 1;
        int u = up * 2 + e, row = g * 70 + u;
        const float* bih = d ? bbih : bfih;
        const float* bhh = d ? bbhh : bfhh;
        float v = bih[row] + bhh[row];
        if (g != 2) v *= 0.5f;
        dB1g[idx] = v;
    }
}

__global__ void prep2(const float* wfih, const float* wfhh, const float* bfih, const float* bfhh,
                      const float* wbih, const float* wbhh, const float* bbih, const float* bbhh) {
    int idx = blockIdx.x * blockDim.x + threadIdx.x;
    if (idx < 2 * 161 * 88) {
        int d = idx / (161 * 88), rem = idx % (161 * 88);
        int k = rem / 88, j = rem % 88;
        int up = j / 8, g = (j / 2) % 4, e = j & 1;
        int u = up * 2 + e;
        float v = 0.f;
        if (u < 21) {
            int row = g * 21 + u;
            const float* wih = d ? wbih : wfih;
            const float* whh = d ? wbhh : wfhh;
            v = (k < 140) ? wih[row * 140 + k] : whh[row * 21 + (k - 140)];
            if (g != 2) v *= 0.5f;
        }
        dW2g[idx] = v;
    }
    if (idx < 2 * 88) {
        int d = idx / 88, j = idx % 88;
        int up = j / 8, g = (j / 2) % 4, e = j & 1;
        int u = up * 2 + e;
        float v = 0.f;
        if (u < 21) {
            int row = g * 21 + u;
            const float* bih = d ? bbih : bfih;
            const float* bhh = d ? bbhh : bfhh;
            v = bih[row] + bhh[row];
            if (g != 2) v *= 0.5f;
        }
        dB2g[idx] = v;
    }
}

// ---------------- layer 1: F=10 -> H=70, bidirectional (R10 form) ----------------
// grid (64, 2), 560 threads = 2 k-groups x 280 (rg 0..7 [4 rows] x up 0..34).
// Non-duplicated acts [k][r32]: act load = 1x LDS.128 (1 wf), dup via MOV (ALU).
__global__ __launch_bounds__(560, 1) void lstm1(const float* __restrict__ x) {
    extern __shared__ float sm[];
    float* sW = sm;                  // 22400
    float* sB = sW + 22400;          // 280
    float* sA = sB + 280;            // 2 * 2560  ([k80][r32] per buffer)
    float* sRed = sA + 5120;         // 2 grp * 8 j * 280 q * 2 = 8960
    const int dir = blockIdx.y, bblk = blockIdx.x;
    const int b0 = bblk * 32;
    const int tid = threadIdx.x;

    const float* gW = dW1g + dir * 22400;
    for (int i = tid; i < 22400; i += 560) sW[i] = gW[i];
    if (tid < 280) sB[tid] = dB1g[dir * 280 + tid];
    for (int i = tid; i < 70 * 32; i += 560) sA[10 * 32 + i] = 0.f;   // h-region buf0

    const int grp = (tid >= 280) ? 1 : 0;
    const int q = tid - 280 * grp;
    const int rg = q & 7, up = q >> 3;
    const int r0 = rg * 4, u0 = up * 2;
    const int rown = r0 + 2 * grp;   // owned rows: rown, rown+1
    const int jo = 2 * grp;          // owned acc idx
    const int jn = 2 - 2 * grp;      // non-owned acc idx

    // stage x(t0) into buffer 0 (non-dup: 1 float per thread, tid<320)
    const int xrow = tid / 10, xf = tid % 10;
    const bool hasx = tid < 320;
    if (hasx) sA[xf * 32 + xrow] = x[((b0 + xrow) * TT + (dir ? TT - 1 : 0)) * 10 + xf];
    float xr = 0.f;
    if (hasx) xr = x[((b0 + xrow) * TT + (dir ? TT - 2 : 1)) * 10 + xf];

    float2 c[2];
    c[0] = make_float2(0.f, 0.f);
    c[1] = make_float2(0.f, 0.f);
    const float* pw = sW + grp * 40 * 280 + up * 8;
    float* sRW = sRed + grp * 8 * 560;            // write: [j][q][2]
    const float* sRR = sRed + (1 - grp) * 8 * 560;
    __syncthreads();

    float2 bf[4];
#pragma unroll
    for (int g = 0; g < 4; g++) bf[g] = *(const float2*)&sB[up * 8 + g * 2];

    int p = 0;
    for (int s = 0; s < TT; s++) {
        const int t = dir ? TT - 1 - s : s;
        const float* pa = sA + p * 2560 + grp * 1280 + r0;

        ull acc[4][4];
#pragma unroll
        for (int r = 0; r < 4; r++)
#pragma unroll
            for (int g = 0; g < 4; g++) acc[r][g] = 0ull;

#pragma unroll 8
        for (int k = 0; k < 40; k++) {
            float4 av = *(const float4*)(pa + k * 32);          // rows r0..r0+3 (1 wf)
            ull a0 = pk2(av.x), a1 = pk2(av.y), a2 = pk2(av.z), a3 = pk2(av.w);
            ulonglong2 w01 = *(const ulonglong2*)(pw + k * 280);       // gates 0,1 (bcast)
            ulonglong2 w23 = *(const ulonglong2*)(pw + k * 280 + 4);   // gates 2,3 (bcast)
            fma2(acc[0][0], a0, w01.x); fma2(acc[0][1], a0, w01.y);
            fma2(acc[0][2], a0, w23.x); fma2(acc[0][3], a0, w23.y);
            fma2(acc[1][0], a1, w01.x); fma2(acc[1][1], a1, w01.y);
            fma2(acc[1][2], a1, w23.x); fma2(acc[1][3], a1, w23.y);
            fma2(acc[2][0], a2, w01.x); fma2(acc[2][1], a2, w01.y);
            fma2(acc[2][2], a2, w23.x); fma2(acc[2][3], a2, w23.y);
            fma2(acc[3][0], a3, w01.x); fma2(acc[3][1], a3, w01.y);
            fma2(acc[3][2], a3, w23.x); fma2(acc[3][3], a3, w23.y);
        }

        // write non-owned 2-row partials (coalesced [j][q] layout)
#pragma unroll
        for (int j = 0; j < 8; j++)
            *(ull*)&sRW[j * 560 + q * 2] = acc[jn + (j >> 2)][j & 3];
        __syncthreads();

        float2 hv[2];
#pragma unroll
        for (int jj = 0; jj < 2; jj++) {
            float2 y[4];
#pragma unroll
            for (int g = 0; g < 4; g++) {
                float2 own = up2(acc[jo + jj][g]);
                float2 pe = up2(*(const ull*)&sRR[(jj * 4 + g) * 560 + q * 2]);
                y[g] = make_float2(own.x + pe.x + bf[g].x, own.y + pe.y + bf[g].y);
            }
            lstm_act(y[0], y[1], y[2], y[3], c[jj], hv[jj]);
        }

        // h(t) -> other buffer (non-dup) + global blocked-transposed
        float* nb = sA + (p ^ 1) * 2560;
        *(float2*)&nb[(10 + u0) * 32 + rown] = make_float2(hv[0].x, hv[1].x);
        *(float2*)&nb[(11 + u0) * 32 + rown] = make_float2(hv[0].y, hv[1].y);
        {
            size_t gb = ((size_t)(bblk * TT + t) * 140 + dir * 70 + u0) * 32 + rown;
            *(float2*)&dH1T[gb]      = make_float2(hv[0].x, hv[1].x);
            *(float2*)&dH1T[gb + 32] = make_float2(hv[0].y, hv[1].y);
        }
        // stage x(t+1) + prefetch x(t+2)
        if (hasx) {
            nb[xf * 32 + xrow] = xr;
            if (s + 2 < TT) {
                int tn = dir ? TT - 3 - s : s + 2;
                xr = x[((b0 + xrow) * TT + tn) * 10 + xf];
            }
        }
        __syncthreads();
        p ^= 1;
    }
}

// ---------------- layer 2: 140 -> H=21 (pad 22), bidirectional ----------------
// grid (64, 2), 352 threads = 4 k-groups x 88 (rg 0..7 [4 rows] x up 0..10).
// 4 rows/thread: 3 LDS per 16 FFMA2 (vs per 8 before) -> crossbar-instr demand
// at fma saturation drops to ~0.26, and per-warp ILP doubles. Thread owns row
// r0+grp, donates the other 3 rows x 4 gates once per step.
#define L2_KLOOP(KN)                                                          \
    _Pragma("unroll 8")                                                       \
    for (int k = 0; k < (KN); k++) {                                          \
        float4 av = *(const float4*)(pa + k * 32);                            \
        ull a0 = pk2(av.x), a1 = pk2(av.y), a2 = pk2(av.z), a3 = pk2(av.w);   \
        ulonglong2 w01 = *(const ulonglong2*)(pw + k * 88);                   \
        ulonglong2 w23 = *(const ulonglong2*)(pw + k * 88 + 4);               \
        fma2(acc[0][0], a0, w01.x); fma2(acc[0][1], a0, w01.y);               \
        fma2(acc[0][2], a0, w23.x); fma2(acc[0][3], a0, w23.y);               \
        fma2(acc[1][0], a1, w01.x); fma2(acc[1][1], a1, w01.y);               \
        fma2(acc[1][2], a1, w23.x); fma2(acc[1][3], a1, w23.y);               \
        fma2(acc[2][0], a2, w01.x); fma2(acc[2][1], a2, w01.y);               \
        fma2(acc[2][2], a2, w23.x); fma2(acc[2][3], a2, w23.y);               \
        fma2(acc[3][0], a3, w01.x); fma2(acc[3][1], a3, w01.y);               \
        fma2(acc[3][2], a3, w23.x); fma2(acc[3][3], a3, w23.y);               \
    }

// sRed float index: [row j(4)][donor slot(3)][gate(4)][q(88)][2]
#define SRED2(j, sl, g, q) (((((j) * 3 + (sl)) * 4 + (g)) * 88 + (q)) * 2)

__global__ __launch_bounds__(352, 1) void lstm2() {
    extern __shared__ float sm[];
    float* sW = sm;                  // 14168
    float* sB = sW + 14168;          // 88
    float* sA = sB + 88;             // 2 * 5152  ([k161][r32] per buffer)
    float* sRed = sA + 10304;        // 4*3*4*88*2 = 8448
    const int dir = blockIdx.y, bblk = blockIdx.x;
    const int tid = threadIdx.x;

    const float* gW = dW2g + dir * 14168;
    for (int i = tid; i < 14168; i += 352) sW[i] = gW[i];
    if (tid < 88) sB[tid] = dB2g[dir * 88 + tid];
    for (int i = tid; i < 21 * 32; i += 352) sA[140 * 32 + i] = 0.f;   // h-region buf0

    // stage h1(t0): 1120 float4 contiguous
    {
        int t0 = dir ? TT - 1 : 0;
        const float4* src = (const float4*)&dH1T[(size_t)(bblk * TT + t0) * 4480];
        float4* dst = (float4*)sA;
#pragma unroll
        for (int j = 0; j < 4; j++) {
            int i = tid + j * 352;
            if (i < 1120) dst[i] = src[i];
        }
    }

    const int grp = tid / 88;
    const int q = tid - 88 * grp;
    const int rg = q & 7, up = q >> 3;
    const int r0 = rg * 4, u0 = up * 2;
    const int rown = r0 + grp;       // owned row

    float2 c = make_float2(0.f, 0.f);
    const int kbeg = grp * 40;
    const float* pw = sW + kbeg * 88 + up * 8;

    // prefetch h1(t1)
    float4 pf[4];
    {
        int t1 = dir ? TT - 2 : 1;
        const float4* src = (const float4*)&dH1T[(size_t)(bblk * TT + t1) * 4480];
#pragma unroll
        for (int j = 0; j < 4; j++) {
            int i = tid + j * 352;
            if (i < 1120) pf[j] = src[i];
        }
    }
    __syncthreads();

    float2 bf[4];
#pragma unroll
    for (int g = 0; g < 4; g++) bf[g] = *(const float2*)&sB[up * 8 + g * 2];

    int p = 0;
    for (int s = 0; s < TT; s++) {
        const int t = dir ? TT - 1 - s : s;
        const float* pa = sA + p * 5152 + kbeg * 32 + r0;

        ull acc[4][4];
#pragma unroll
        for (int r = 0; r < 4; r++)
#pragma unroll
            for (int g = 0; g < 4; g++) acc[r][g] = 0ull;

        if (grp == 3) { L2_KLOOP(41) } else { L2_KLOOP(40) }

        // donate the 3 non-owned rows (coalesced along q)
#pragma unroll
        for (int jj = 0; jj < 4; jj++) {
            if (jj != grp) {
                int sl = (grp < jj) ? grp : grp - 1;
#pragma unroll
                for (int g = 0; g < 4; g++)
                    *(ull*)&sRed[SRED2(jj, sl, g, q)] = acc[jj][g];
            }
        }
        __syncthreads();

        // finalize owned row: own + 3 donations + bias
        float2 y[4];
#pragma unroll
        for (int g = 0; g < 4; g++) {
            float2 own = up2(acc[grp][g]);
            float2 p0 = up2(*(const ull*)&sRed[SRED2(grp, 0, g, q)]);
            float2 p1 = up2(*(const ull*)&sRed[SRED2(grp, 1, g, q)]);
            float2 p2 = up2(*(const ull*)&sRed[SRED2(grp, 2, g, q)]);
            y[g] = make_float2(own.x + p0.x + p1.x + p2.x + bf[g].x,
                               own.y + p0.y + p1.y + p2.y + bf[g].y);
        }
        float2 h;
        lstm_act(y[0], y[1], y[2], y[3], c, h);

        // h -> other buffer + global dH2 [bblk][t][42][r32] (coalesced)
        float* nb = sA + (p ^ 1) * 5152;
        nb[(140 + u0) * 32 + rown] = h.x;
        if (u0 + 1 < 21) nb[(141 + u0) * 32 + rown] = h.y;
        {
            size_t ob = ((size_t)(bblk * TT + t) * 42 + dir * 21 + u0) * 32 + rown;
            dH2[ob] = h.x;
            if (u0 + 1 < 21) dH2[ob + 32] = h.y;
        }

        // stage h1(t+1) into other buffer (contiguous STS.128)
        if (s + 1 < TT) {
            float4* dst = (float4*)nb;
#pragma unroll
            for (int j = 0; j < 4; j++) {
                int i = tid + j * 352;
                if (i < 1120) dst[i] = pf[j];
            }
        }
        // prefetch h1(t+2)
        if (s + 2 < TT) {
            int tn = dir ? TT - 3 - s : s + 2;
            const float4* src = (const float4*)&dH1T[(size_t)(bblk * TT + tn) * 4480];
#pragma unroll
            for (int j = 0; j < 4; j++) {
                int i = tid + j * 352;
                if (i < 1120) pf[j] = src[i];
            }
        }
        __syncthreads();
        p ^= 1;
    }
}

// ---------------- dense head: 42 -> relu 30 -> relu 20 -> 1 ----------------
__global__ __launch_bounds__(128) void dense_head(const float* __restrict__ wd1, const float* __restrict__ bd1,
                                                  const float* __restrict__ wd2, const float* __restrict__ bd2,
                                                  const float* __restrict__ wo, const float* __restrict__ bo,
                                                  float* __restrict__ out) {
    __shared__ float sT[4 * 42 * 32];
    __shared__ float sW1[30 * 42], sb1[30], sW2[20 * 30], sb2[20], swo[20], sbo[1];
    const int tid = threadIdx.x;
    const int bblk = blockIdx.x, t0 = blockIdx.y * 4;

    {
        const float4* src = (const float4*)&dH2[(size_t)(bblk * TT + t0) * 1344];
        float4* dst = (float4*)sT;
#pragma unroll
        for (int j = 0; j < 11; j++) {
            int i = tid + j * 128;
            if (i < 1344) dst[i] = src[i];
        }
    }
    for (int i = tid; i < 1260; i += 128) sW1[i] = wd1[i];
    for (int i = tid; i < 600; i += 128) sW2[i] = wd2[i];
    if (tid < 30) sb1[tid] = bd1[tid];
    if (tid < 20) { sb2[tid] = bd2[tid]; swo[tid] = wo[tid]; }
    if (tid == 0) sbo[0] = bo[0];
    __syncthreads();

    const int t = tid >> 5, r = tid & 31;
    float in[42];
#pragma unroll
    for (int u = 0; u < 42; u++) in[u] = sT[(t * 42 + u) * 32 + r];

    float a[30];
#pragma unroll
    for (int j = 0; j < 30; j++) {
        float s = sb1[j];
#pragma unroll
        for (int k = 0; k < 42; k++) s += in[k] * sW1[j * 42 + k];
        a[j] = fmaxf(s, 0.f);
    }
    float o = sbo[0];
#pragma unroll
    for (int j = 0; j < 20; j++) {
        float s = sb2[j];
#pragma unroll
        for (int k = 0; k < 30; k++) s += a[k] * sW2[j * 30 + k];
        o += fmaxf(s, 0.f) * swo[j];
    }
    out[(size_t)(bblk * 32 + r) * TT + t0 + t] = o;
}

// ---------------- launch ----------------
extern "C" void kernel_launch(void* const* d_in, const int* in_sizes, int n_in,
                              void* d_out, int out_size) {
    const float* x = (const float*)d_in[0];

    const int smem1 = (22400 + 280 + 2 * 2560 + 8960) * 4;   // 147040 B
    const int smem2 = (14168 + 88 + 2 * 5152 + 8448) * 4;    // 132032 B
    cudaFuncSetAttribute(lstm1, cudaFuncAttributeMaxDynamicSharedMemorySize, smem1);
    cudaFuncSetAttribute(lstm2, cudaFuncAttributeMaxDynamicSharedMemorySize, smem2);

    prep1<<<175, 256>>>((const float*)d_in[1], (const float*)d_in[2], (const float*)d_in[3], (const float*)d_in[4],
                        (const float*)d_in[5], (const float*)d_in[6], (const float*)d_in[7], (const float*)d_in[8]);
    prep2<<<111, 256>>>((const float*)d_in[9], (const float*)d_in[10], (const float*)d_in[11], (const float*)d_in[12],
                        (const float*)d_in[13], (const float*)d_in[14], (const float*)d_in[15], (const float*)d_in[16]);

    lstm1<<<dim3(64, 2), 560, smem1>>>(x);
    lstm2<<<dim3(64, 2), 352, smem2>>>();

    dense_head<<<dim3(64, 84), 128>>>((const float*)d_in[17], (const float*)d_in[18],
                                      (const float*)d_in[19], (const float*)d_in[20],
                                      (const float*)d_in[21], (const float*)d_in[22],
                                      (float*)d_out);
}